// round 3
// baseline (speedup 1.0000x reference)
#include <cuda_runtime.h>
#include <math.h>

#define NN 100000
#define EE 1600000
#define FIN 64
#define HH 32

// ---------------- device scratch (static, allocation-free) ----------------
__device__ __align__(16) float g_xr[NN * HH];     // rel-transformed features for edge pass
__device__ __align__(16) float g_rt[NN * HH];     // root-transformed features (+bias)
__device__ __align__(16) float g_agg[NN * HH];    // scatter-add aggregation buffer
__device__ __align__(16) float g_pvsrc[NN * 2];   // per-node (h2 . Wp_rel, h2 . Wv_rel)
__device__ __align__(16) float g_pvrt[NN * 2];    // per-node (h2 . Wp_root + bp, h2 . Wv_root + bv)
__device__ __align__(16) float g_pvagg[NN * 2];   // aggregated (p, v)
__device__ __align__(16) float g_mask[NN];
__device__ __align__(16) float g_pm[NN];
__device__ unsigned g_maxkey;
__device__ float g_sum;

// ---------------- fused: xr = x@Win_rel, rt = x@Win_root + bin, zero scratch ----------------
__global__ void k_xw64f(const float* __restrict__ x, const float* __restrict__ Wrel,
                        const float* __restrict__ Wroot, const float* __restrict__ b) {
    __shared__ float sWa[FIN * HH];
    __shared__ float sWb[FIN * HH];
    __shared__ float sb[HH];
    for (int i = threadIdx.x; i < FIN * HH; i += blockDim.x) {
        sWa[i] = Wrel[i];
        sWb[i] = Wroot[i];
    }
    if (threadIdx.x < HH) sb[threadIdx.x] = b[threadIdx.x];
    __syncthreads();
    int node = blockIdx.x * blockDim.x + threadIdx.x;
    if (node == 0) { g_maxkey = 0u; g_sum = 0.f; }
    if (node >= NN) return;
    float ar[HH], br[HH];
#pragma unroll
    for (int j = 0; j < HH; j++) { ar[j] = 0.f; br[j] = sb[j]; }
    const float4* xv = (const float4*)(x + (size_t)node * FIN);
#pragma unroll
    for (int k4 = 0; k4 < FIN / 4; k4++) {
        float4 xk = xv[k4];
        float xs[4] = {xk.x, xk.y, xk.z, xk.w};
#pragma unroll
        for (int kk = 0; kk < 4; kk++) {
            const float4* wa = (const float4*)(sWa + (k4 * 4 + kk) * HH);
            const float4* wb = (const float4*)(sWb + (k4 * 4 + kk) * HH);
#pragma unroll
            for (int j4 = 0; j4 < HH / 4; j4++) {
                float4 a = wa[j4];
                float4 bb = wb[j4];
                ar[j4 * 4 + 0] += xs[kk] * a.x;  br[j4 * 4 + 0] += xs[kk] * bb.x;
                ar[j4 * 4 + 1] += xs[kk] * a.y;  br[j4 * 4 + 1] += xs[kk] * bb.y;
                ar[j4 * 4 + 2] += xs[kk] * a.z;  br[j4 * 4 + 2] += xs[kk] * bb.z;
                ar[j4 * 4 + 3] += xs[kk] * a.w;  br[j4 * 4 + 3] += xs[kk] * bb.w;
            }
        }
    }
    float4* oa = (float4*)(g_xr + (size_t)node * HH);
    float4* ob = (float4*)(g_rt + (size_t)node * HH);
    float4* oz = (float4*)(g_agg + (size_t)node * HH);
    float4 z = make_float4(0.f, 0.f, 0.f, 0.f);
#pragma unroll
    for (int j4 = 0; j4 < HH / 4; j4++) {
        oa[j4] = make_float4(ar[j4 * 4], ar[j4 * 4 + 1], ar[j4 * 4 + 2], ar[j4 * 4 + 3]);
        ob[j4] = make_float4(br[j4 * 4], br[j4 * 4 + 1], br[j4 * 4 + 2], br[j4 * 4 + 3]);
        oz[j4] = z;
    }
    g_mask[node] = 0.f;
    *(float2*)(g_pvagg + (size_t)node * 2) = make_float2(0.f, 0.f);
}

// ---------------- edge scatter-add of 32-float rows (8 threads / edge) ----------------
__global__ void k_edge32(const int* __restrict__ ei, const float* __restrict__ ew,
                         const int* __restrict__ curp, int do_mask) {
    long long g = (long long)blockIdx.x * blockDim.x + threadIdx.x;
    if (g >= (long long)EE * 8) return;
    int e = (int)(g >> 3);
    int c = (int)(g & 7);
    int s = __ldg(ei + e);
    int d = __ldg(ei + EE + e);
    float w = __ldg(ew + e);
    float4 v = ((const float4*)(g_xr + (size_t)s * HH))[c];
    float* p = g_agg + (size_t)d * HH + c * 4;
    asm volatile("red.global.add.v4.f32 [%0], {%1,%2,%3,%4};"
                 :: "l"(p), "f"(v.x * w), "f"(v.y * w), "f"(v.z * w), "f"(v.w * w)
                 : "memory");
    if (do_mask && c == 0 && s == __ldg(curp)) g_mask[d] = 1.0f;
}

// ---------------- h1 = relu(agg + rt); g_xr = h1@Wh_rel; g_rt = h1@Wh_root + bh; agg = 0 ----------------
__global__ void k_node1(const float* __restrict__ Whrel, const float* __restrict__ Whroot,
                        const float* __restrict__ bh) {
    __shared__ float sWa[HH * HH];
    __shared__ float sWb[HH * HH];
    __shared__ float sb[HH];
    for (int i = threadIdx.x; i < HH * HH; i += blockDim.x) {
        sWa[i] = Whrel[i];
        sWb[i] = Whroot[i];
    }
    if (threadIdx.x < HH) sb[threadIdx.x] = bh[threadIdx.x];
    __syncthreads();
    int node = blockIdx.x * blockDim.x + threadIdx.x;
    if (node >= NN) return;
    float h1[HH];
    float4* av = (float4*)(g_agg + (size_t)node * HH);
    const float4* rv = (const float4*)(g_rt + (size_t)node * HH);
    float4 z = make_float4(0.f, 0.f, 0.f, 0.f);
#pragma unroll
    for (int j4 = 0; j4 < HH / 4; j4++) {
        float4 a = av[j4];
        float4 r = rv[j4];
        h1[j4 * 4 + 0] = fmaxf(a.x + r.x, 0.f);
        h1[j4 * 4 + 1] = fmaxf(a.y + r.y, 0.f);
        h1[j4 * 4 + 2] = fmaxf(a.z + r.z, 0.f);
        h1[j4 * 4 + 3] = fmaxf(a.w + r.w, 0.f);
        av[j4] = z;  // fused zeroing for edge pass 2
    }
    float acc[HH];
    // h1 @ Wh_rel -> g_xr
#pragma unroll
    for (int j = 0; j < HH; j++) acc[j] = 0.f;
#pragma unroll
    for (int k = 0; k < HH; k++) {
        float hk = h1[k];
        const float4* w4 = (const float4*)(sWa + k * HH);
#pragma unroll
        for (int j4 = 0; j4 < HH / 4; j4++) {
            float4 w = w4[j4];
            acc[j4 * 4 + 0] += hk * w.x;
            acc[j4 * 4 + 1] += hk * w.y;
            acc[j4 * 4 + 2] += hk * w.z;
            acc[j4 * 4 + 3] += hk * w.w;
        }
    }
    float4* oa = (float4*)(g_xr + (size_t)node * HH);
#pragma unroll
    for (int j4 = 0; j4 < HH / 4; j4++)
        oa[j4] = make_float4(acc[j4 * 4], acc[j4 * 4 + 1], acc[j4 * 4 + 2], acc[j4 * 4 + 3]);
    // h1 @ Wh_root + bh -> g_rt
#pragma unroll
    for (int j = 0; j < HH; j++) acc[j] = sb[j];
#pragma unroll
    for (int k = 0; k < HH; k++) {
        float hk = h1[k];
        const float4* w4 = (const float4*)(sWb + k * HH);
#pragma unroll
        for (int j4 = 0; j4 < HH / 4; j4++) {
            float4 w = w4[j4];
            acc[j4 * 4 + 0] += hk * w.x;
            acc[j4 * 4 + 1] += hk * w.y;
            acc[j4 * 4 + 2] += hk * w.z;
            acc[j4 * 4 + 3] += hk * w.w;
        }
    }
    float4* ob = (float4*)(g_rt + (size_t)node * HH);
#pragma unroll
    for (int j4 = 0; j4 < HH / 4; j4++)
        ob[j4] = make_float4(acc[j4 * 4], acc[j4 * 4 + 1], acc[j4 * 4 + 2], acc[j4 * 4 + 3]);
}

// ---------------- h2 = relu(agg + rt); pvsrc = (h2.Wp_rel, h2.Wv_rel); pvrt = (h2.Wp_root+bp, h2.Wv_root+bv) ----------------
__global__ void k_node2(const float* __restrict__ Wprel, const float* __restrict__ Wvrel,
                        const float* __restrict__ Wproot, const float* __restrict__ Wvroot,
                        const float* __restrict__ bp, const float* __restrict__ bv) {
    __shared__ float sWpr[HH], sWvr[HH], sWpo[HH], sWvo[HH];
    if (threadIdx.x < HH) {
        sWpr[threadIdx.x] = Wprel[threadIdx.x];
        sWvr[threadIdx.x] = Wvrel[threadIdx.x];
        sWpo[threadIdx.x] = Wproot[threadIdx.x];
        sWvo[threadIdx.x] = Wvroot[threadIdx.x];
    }
    __syncthreads();
    int node = blockIdx.x * blockDim.x + threadIdx.x;
    if (node >= NN) return;
    const float4* av = (const float4*)(g_agg + (size_t)node * HH);
    const float4* rv = (const float4*)(g_rt + (size_t)node * HH);
    float pr = 0.f, vr = 0.f, po = bp[0], vo = bv[0];
#pragma unroll
    for (int j4 = 0; j4 < HH / 4; j4++) {
        float4 a = av[j4];
        float4 r = rv[j4];
        float h0 = fmaxf(a.x + r.x, 0.f);
        float h1 = fmaxf(a.y + r.y, 0.f);
        float h2 = fmaxf(a.z + r.z, 0.f);
        float h3 = fmaxf(a.w + r.w, 0.f);
        int j = j4 * 4;
        pr += h0 * sWpr[j] + h1 * sWpr[j + 1] + h2 * sWpr[j + 2] + h3 * sWpr[j + 3];
        vr += h0 * sWvr[j] + h1 * sWvr[j + 1] + h2 * sWvr[j + 2] + h3 * sWvr[j + 3];
        po += h0 * sWpo[j] + h1 * sWpo[j + 1] + h2 * sWpo[j + 2] + h3 * sWpo[j + 3];
        vo += h0 * sWvo[j] + h1 * sWvo[j + 1] + h2 * sWvo[j + 2] + h3 * sWvo[j + 3];
    }
    *(float2*)(g_pvsrc + (size_t)node * 2) = make_float2(pr, vr);
    *(float2*)(g_pvrt + (size_t)node * 2) = make_float2(po, vo);
}

// ---------------- edge pass for p/v heads: 2 floats/edge ----------------
__global__ void k_edge_pv(const int* __restrict__ ei, const float* __restrict__ ew) {
    int e = blockIdx.x * blockDim.x + threadIdx.x;
    if (e >= EE) return;
    int s = __ldg(ei + e);
    int d = __ldg(ei + EE + e);
    float w = __ldg(ew + e);
    float2 pv = *(const float2*)(g_pvsrc + (size_t)s * 2);
    float* p = g_pvagg + (size_t)d * 2;
    asm volatile("red.global.add.v2.f32 [%0], {%1,%2};"
                 :: "l"(p), "f"(pv.x * w), "f"(pv.y * w) : "memory");
}

// ---------------- finalize p/v, mask, softmax max ----------------
__global__ void k_final_a(float* __restrict__ out) {
    int node = blockIdx.x * blockDim.x + threadIdx.x;
    unsigned key = 0u;
    if (node < NN) {
        float2 agg = *(const float2*)(g_pvagg + (size_t)node * 2);
        float2 rt = *(const float2*)(g_pvrt + (size_t)node * 2);
        float p = agg.x + rt.x;
        float v = agg.y + rt.y;
        float m = g_mask[node];
        float pm = m * p;
        if (pm == 0.f) pm = __int_as_float(0xFF800000);   // -inf, matching jnp.where(p_m==0, -inf, p_m)
        g_pm[node] = pm;
        out[NN + node] = m * v;
        unsigned bb = __float_as_uint(pm);
        key = (bb & 0x80000000u) ? ~bb : (bb | 0x80000000u);  // order-preserving key
    }
    unsigned wmax = __reduce_max_sync(0xFFFFFFFFu, key);
    if ((threadIdx.x & 31) == 0 && wmax) atomicMax(&g_maxkey, wmax);
}

// ---------------- softmax exp + sum ----------------
__global__ void k_final_b(float* __restrict__ out) {
    int node = blockIdx.x * blockDim.x + threadIdx.x;
    float e = 0.f;
    if (node < NN) {
        unsigned k = g_maxkey;
        float maxv = __uint_as_float((k & 0x80000000u) ? (k ^ 0x80000000u) : ~k);
        e = expf(g_pm[node] - maxv);
        out[node] = e;
    }
#pragma unroll
    for (int o = 16; o; o >>= 1) e += __shfl_xor_sync(0xFFFFFFFFu, e, o);
    if ((threadIdx.x & 31) == 0 && e != 0.f) atomicAdd(&g_sum, e);
}

// ---------------- softmax normalize ----------------
__global__ void k_final_c(float* __restrict__ out) {
    int node = blockIdx.x * blockDim.x + threadIdx.x;
    if (node < NN) out[node] = out[node] / g_sum;
}

// ---------------- launch ----------------
extern "C" void kernel_launch(void* const* d_in, const int* in_sizes, int n_in,
                              void* d_out, int out_size) {
    const float* x        = (const float*)d_in[0];
    const int*   ei       = (const int*)d_in[1];
    const float* ew       = (const float*)d_in[2];
    const int*   cur      = (const int*)d_in[3];
    const float* Win_rel  = (const float*)d_in[4];
    const float* bin_rel  = (const float*)d_in[5];
    const float* Win_root = (const float*)d_in[6];
    const float* Wh_rel   = (const float*)d_in[7];
    const float* bh_rel   = (const float*)d_in[8];
    const float* Wh_root  = (const float*)d_in[9];
    const float* Wp_rel   = (const float*)d_in[10];
    const float* bp_rel   = (const float*)d_in[11];
    const float* Wp_root  = (const float*)d_in[12];
    const float* Wv_rel   = (const float*)d_in[13];
    const float* bv_rel   = (const float*)d_in[14];
    const float* Wv_root  = (const float*)d_in[15];
    float* out = (float*)d_out;

    const int TB = 256;
    const int gn = (NN + TB - 1) / TB;
    const int ge8 = (int)(((long long)EE * 8 + TB - 1) / TB);
    const int ge = (EE + TB - 1) / TB;

    k_xw64f<<<gn, TB>>>(x, Win_rel, Win_root, bin_rel);
    k_edge32<<<ge8, TB>>>(ei, ew, cur, 1);
    k_node1<<<gn, TB>>>(Wh_rel, Wh_root, bh_rel);
    k_edge32<<<ge8, TB>>>(ei, ew, cur, 0);
    k_node2<<<gn, TB>>>(Wp_rel, Wv_rel, Wp_root, Wv_root, bp_rel, bv_rel);
    k_edge_pv<<<ge, TB>>>(ei, ew);
    k_final_a<<<gn, TB>>>(out);
    k_final_b<<<gn, TB>>>(out);
    k_final_c<<<gn, TB>>>(out);
}